// round 16
// baseline (speedup 1.0000x reference)
#include <cuda_runtime.h>

typedef unsigned long long ULL;

__device__ __forceinline__ ULL fma2(ULL a, ULL b, ULL c) {
    ULL d;
    asm("fma.rn.f32x2 %0, %1, %2, %3;" : "=l"(d) : "l"(a), "l"(b), "l"(c));
    return d;
}
__device__ __forceinline__ ULL dup2(float x) {
    ULL d;
    asm("mov.b64 %0, {%1, %1};" : "=l"(d) : "f"(x));
    return d;
}
__device__ __forceinline__ float2 unpk(ULL v) {
    float2 r;
    asm("mov.b64 {%0, %1}, %2;" : "=f"(r.x), "=f"(r.y) : "l"(v));
    return r;
}

#define N_TOT 8192
#define TN 8          // n's per block

// Scratch (static device globals — no allocation)
__device__ __align__(16) float4 g_ca4[8 * 512];   // [k2][p] : h1 cols 4k2..4k2+3

// ---------------------------------------------------------------------------
__global__ void pre_ca(const float* __restrict__ cx, const float* __restrict__ Wa1) {
    int idx = blockIdx.x * blockDim.x + threadIdx.x;   // 4096 = 512p * 8k2
    int p = idx & 511, k2 = idx >> 9;
    float x0 = cx[p * 2 + 0], x1 = cx[p * 2 + 1];
    int j = 4 * k2;
    float4 v;
    v.x = x0 * Wa1[64 + j + 0] + x1 * Wa1[96 + j + 0];
    v.y = x0 * Wa1[64 + j + 1] + x1 * Wa1[96 + j + 1];
    v.z = x0 * Wa1[64 + j + 2] + x1 * Wa1[96 + j + 2];
    v.w = x0 * Wa1[64 + j + 3] + x1 * Wa1[96 + j + 3];
    g_ca4[k2 * 512 + p] = v;
}

// one k-row step: h1 for 4 p's against a 16-j Wa2 row slice (4 LDS.128)
__device__ __forceinline__ void step4(float qs, float c0, float c1, float c2, float c3,
                                      const float* wrow, ULL acc[4][8]) {
    ULL h0 = dup2(fmaxf(qs + c0, 0.f));
    ULL h1 = dup2(fmaxf(qs + c1, 0.f));
    ULL h2 = dup2(fmaxf(qs + c2, 0.f));
    ULL h3 = dup2(fmaxf(qs + c3, 0.f));
    const ulonglong2* wr = reinterpret_cast<const ulonglong2*>(wrow);
    ulonglong2 wA = wr[0], wB = wr[1], wC = wr[2], wD = wr[3];
    acc[0][0] = fma2(h0, wA.x, acc[0][0]); acc[0][1] = fma2(h0, wA.y, acc[0][1]);
    acc[0][2] = fma2(h0, wB.x, acc[0][2]); acc[0][3] = fma2(h0, wB.y, acc[0][3]);
    acc[0][4] = fma2(h0, wC.x, acc[0][4]); acc[0][5] = fma2(h0, wC.y, acc[0][5]);
    acc[0][6] = fma2(h0, wD.x, acc[0][6]); acc[0][7] = fma2(h0, wD.y, acc[0][7]);
    acc[1][0] = fma2(h1, wA.x, acc[1][0]); acc[1][1] = fma2(h1, wA.y, acc[1][1]);
    acc[1][2] = fma2(h1, wB.x, acc[1][2]); acc[1][3] = fma2(h1, wB.y, acc[1][3]);
    acc[1][4] = fma2(h1, wC.x, acc[1][4]); acc[1][5] = fma2(h1, wC.y, acc[1][5]);
    acc[1][6] = fma2(h1, wD.x, acc[1][6]); acc[1][7] = fma2(h1, wD.y, acc[1][7]);
    acc[2][0] = fma2(h2, wA.x, acc[2][0]); acc[2][1] = fma2(h2, wA.y, acc[2][1]);
    acc[2][2] = fma2(h2, wB.x, acc[2][2]); acc[2][3] = fma2(h2, wB.y, acc[2][3]);
    acc[2][4] = fma2(h2, wC.x, acc[2][4]); acc[2][5] = fma2(h2, wC.y, acc[2][5]);
    acc[2][6] = fma2(h2, wD.x, acc[2][6]); acc[2][7] = fma2(h2, wD.y, acc[2][7]);
    acc[3][0] = fma2(h3, wA.x, acc[3][0]); acc[3][1] = fma2(h3, wA.y, acc[3][1]);
    acc[3][2] = fma2(h3, wB.x, acc[3][2]); acc[3][3] = fma2(h3, wB.y, acc[3][3]);
    acc[3][4] = fma2(h3, wC.x, acc[3][4]); acc[3][5] = fma2(h3, wC.y, acc[3][5]);
    acc[3][6] = fma2(h3, wD.x, acc[3][6]); acc[3][7] = fma2(h3, wD.y, acc[3][7]);
}

// ---------------------------------------------------------------------------
// FUSED kernel. 256 threads, 2 blocks/SM. Thread tile: 1n x 4p x 16j.
// In-loop: shuffle-reduce + sRedAll write + ONE barrier (spill fence).
// ALL projections batched into one end phase; then fused gating.
__global__ __launch_bounds__(256, 2) void fused_kernel(
    const float* __restrict__ r,
    const float* __restrict__ rp,
    const float* __restrict__ coeff_y,
    const float* __restrict__ Wa1,
    const float* __restrict__ Wa2,
    const float* __restrict__ Wa3,
    const float* __restrict__ Wp1, const float* __restrict__ bp1,
    const float* __restrict__ Wp2, const float* __restrict__ bp2,
    const float* __restrict__ Wg1, const float* __restrict__ bg1,
    const float* __restrict__ Wg2, const float* __restrict__ bg2,
    const float* __restrict__ Wg3, const float* __restrict__ bg3,
    float* __restrict__ out)
{
    __shared__ __align__(16) float sWa2[1024];
    __shared__ __align__(16) float2 sQa[TN][16];
    __shared__ __align__(8)  float sWa3[32];
    __shared__ float sRedAll[TN][8][5];          // per-n per-warp partials
    __shared__ float sPool[TN][5];
    __shared__ float sHp[TN][32];
    __shared__ float sC[TN][16];
    __shared__ float sX[TN][25];
    __shared__ __align__(16) float sG1[256 * 8];
    __shared__ float sPart[8][8];

    const int tid  = threadIdx.x;
    const int lane = tid & 31, warp = tid >> 5;
    const int pg   = warp * 16 + (lane & 15);   // 0..127
    const int jh   = lane >> 4;                 // 0 or 1
    const int n0 = blockIdx.x * TN;

#pragma unroll
    for (int i = 0; i < 4; ++i) sWa2[tid + 256 * i] = Wa2[tid + 256 * i];
    if (tid < 32) sWa3[tid] = Wa3[tid];
    if (tid < TN * 16) {
        int t = tid >> 4, k = tid & 15;
        int n = n0 + t;
        float x0 = r[n * 4 + 0], x1 = r[n * 4 + 1];
        float q0 = x0 * Wa1[2 * k]     + x1 * Wa1[32 + 2 * k];
        float q1 = x0 * Wa1[2 * k + 1] + x1 * Wa1[32 + 2 * k + 1];
        sQa[t][k] = make_float2(q0, q1);
    }
    __syncthreads();

    const float* wbase = sWa2 + 16 * jh;            // j-slice base
    const float2* w3p = reinterpret_cast<const float2*>(sWa3) + 8 * jh;
    const float4* cyp = reinterpret_cast<const float4*>(coeff_y);

    // ================= attention phase =================
#pragma unroll 1
    for (int t = 0; t < TN; ++t) {
        const float4* qa4 = reinterpret_cast<const float4*>(sQa[t]);

        ULL acc[4][8];
#pragma unroll
        for (int i = 0; i < 4; ++i)
#pragma unroll
            for (int q = 0; q < 8; ++q) acc[i][q] = 0ull;

#pragma unroll 4
        for (int k2 = 0; k2 < 8; ++k2) {
            float4 ca0 = g_ca4[k2 * 512 + pg];
            float4 ca1 = g_ca4[k2 * 512 + pg + 128];
            float4 ca2 = g_ca4[k2 * 512 + pg + 256];
            float4 ca3 = g_ca4[k2 * 512 + pg + 384];
            float4 qa  = qa4[k2];                     // broadcast LDS.128
            step4(qa.x, ca0.x, ca1.x, ca2.x, ca3.x, wbase + (4 * k2 + 0) * 32, acc);
            step4(qa.y, ca0.y, ca1.y, ca2.y, ca3.y, wbase + (4 * k2 + 1) * 32, acc);
            step4(qa.z, ca0.z, ca1.z, ca2.z, ca3.z, wbase + (4 * k2 + 2) * 32, acc);
            step4(qa.w, ca0.w, ca1.w, ca2.w, ca3.w, wbase + (4 * k2 + 3) * 32, acc);
        }

        // partial logits over this thread's 16 j's, for 4 p's
        float lg[4] = {0.f, 0.f, 0.f, 0.f};
#pragma unroll
        for (int q = 0; q < 8; ++q) {
            float2 w = w3p[q];
#pragma unroll
            for (int i = 0; i < 4; ++i) {
                float2 a = unpk(acc[i][q]);
                lg[i] += fmaxf(a.x, 0.f) * w.x + fmaxf(a.y, 0.f) * w.y;
            }
        }
        // combine j-halves with partner lane (lane ^ 16)
#pragma unroll
        for (int i = 0; i < 4; ++i)
            lg[i] += __shfl_xor_sync(0xffffffffu, lg[i], 16);

        // ===== thin epilogue: exp + weighted sums, ONE barrier =====
        float e0 = __expf(lg[0]);
        float e1 = __expf(lg[1]);
        float e2 = __expf(lg[2]);
        float e3 = __expf(lg[3]);
        float4 cy0 = cyp[pg];
        float4 cy1 = cyp[pg + 128];
        float4 cy2 = cyp[pg + 256];
        float4 cy3 = cyp[pg + 384];
        // each p appears twice across the warp (jh pair) -> factor 2 cancels
        float v0 = e0 + e1 + e2 + e3;
        float v1 = e0 * cy0.x + e1 * cy1.x + e2 * cy2.x + e3 * cy3.x;
        float v2 = e0 * cy0.y + e1 * cy1.y + e2 * cy2.y + e3 * cy3.y;
        float v3 = e0 * cy0.z + e1 * cy1.z + e2 * cy2.z + e3 * cy3.z;
        float v4 = e0 * cy0.w + e1 * cy1.w + e2 * cy2.w + e3 * cy3.w;
#pragma unroll
        for (int off = 16; off; off >>= 1) {
            v0 += __shfl_xor_sync(0xffffffffu, v0, off);
            v1 += __shfl_xor_sync(0xffffffffu, v1, off);
            v2 += __shfl_xor_sync(0xffffffffu, v2, off);
            v3 += __shfl_xor_sync(0xffffffffu, v3, off);
            v4 += __shfl_xor_sync(0xffffffffu, v4, off);
        }
        if (lane == 0) {
            sRedAll[t][warp][0] = v0; sRedAll[t][warp][1] = v1;
            sRedAll[t][warp][2] = v2; sRedAll[t][warp][3] = v3;
            sRedAll[t][warp][4] = v4;
        }
        __syncthreads();     // spill fence (proven necessary) + sRedAll publish
    }

    // ================= batched projection for all 8 n's =================
    if (tid < TN * 5) {
        int t = tid / 5, j = tid % 5;
        float s = 0.f;
#pragma unroll
        for (int w = 0; w < 8; ++w) s += sRedAll[t][w][j];
        sPool[t][j] = s;
    }
    __syncthreads();
    {   // hp for all 8 n's: 256 threads = 8n x 32j
        int u = tid >> 5, j = tid & 31;
        float inv = 1.f / sPool[u][0];
        float a0 = sPool[u][1] * inv, a1 = sPool[u][2] * inv;
        float a2 = sPool[u][3] * inv, a3 = sPool[u][4] * inv;
        float hp = bp1[j] + a0 * Wp1[j] + a1 * Wp1[32 + j]
                          + a2 * Wp1[64 + j] + a3 * Wp1[96 + j];
        sHp[u][j] = fmaxf(hp, 0.f);
    }
    __syncthreads();
    if (tid < TN * 16) {
        int u = tid >> 4, j = tid & 15;
        float cv = bp2[j];
#pragma unroll
        for (int k = 0; k < 32; ++k) cv += sHp[u][k] * Wp2[k * 16 + j];
        sC[u][j] = cv;
    }
    __syncthreads();

    // ================= gate phase (fused; rows = this block's 8 n's) =======
    if (tid < TN * 24) {
        int row = tid / 24, j = tid % 24;
        int n = n0 + row;
        float v = (j < 4) ? r[n * 4 + j]
                : (j < 8) ? rp[n * 4 + (j - 4)]
                          : sC[row][j - 8];
        sX[row][j] = v;
    }
    __syncthreads();

    // Stage A: warp w -> k in [32w, 32w+32); lane -> (row = lane&7, kq = lane>>3)
    {
        const int row = lane & 7, kq = lane >> 3;   // kq 0..3
        float x[24];
#pragma unroll
        for (int j = 0; j < 24; ++j) x[j] = sX[row][j];
        const int kbase = warp * 32 + kq;
#pragma unroll 4
        for (int kk = 0; kk < 8; ++kk) {
            int k = kbase + 4 * kk;
            float a = bg1[k];
#pragma unroll
            for (int j = 0; j < 24; ++j) a += x[j] * Wg1[j * 256 + k];
            sG1[k * 8 + row] = fmaxf(a, 0.f);
        }
    }
    __syncthreads();

    // Stage B: lane owns one j column; 8 rows packed in 4 ULL accs
    const int jcol = warp * 32 + lane;

    ULL acc[4];
    {
        ULL b2 = dup2(bg2[jcol]);
#pragma unroll
        for (int i = 0; i < 4; ++i) acc[i] = b2;
    }

    const float* wcol = Wg2 + jcol;
    const ulonglong2* gRows = reinterpret_cast<const ulonglong2*>(sG1);

#pragma unroll 8
    for (int k = 0; k < 256; ++k) {
        ULL w2 = dup2(wcol[k * 256]);        // coalesced LDG.32
        ulonglong2 g01 = gRows[k * 2 + 0];   // rows 0-3 (broadcast LDS.128)
        ulonglong2 g23 = gRows[k * 2 + 1];   // rows 4-7
        acc[0] = fma2(g01.x, w2, acc[0]);
        acc[1] = fma2(g01.y, w2, acc[1]);
        acc[2] = fma2(g23.x, w2, acc[2]);
        acc[3] = fma2(g23.y, w2, acc[3]);
    }

    // epilogue: relu, * Wg3, reduce across lanes (j), then across warps
    float w3 = Wg3[jcol];
    float rv[8];
#pragma unroll
    for (int i = 0; i < 4; ++i) {
        float2 a = unpk(acc[i]);
        rv[2 * i]     = fmaxf(a.x, 0.f) * w3;
        rv[2 * i + 1] = fmaxf(a.y, 0.f) * w3;
    }
#pragma unroll
    for (int off = 16; off; off >>= 1) {
#pragma unroll
        for (int i = 0; i < 8; ++i)
            rv[i] += __shfl_xor_sync(0xffffffffu, rv[i], off);
    }
    if (lane == 0) {
#pragma unroll
        for (int i = 0; i < 8; ++i) sPart[warp][i] = rv[i];
    }
    __syncthreads();

    if (tid < 8) {
        float s = bg3[0];
#pragma unroll
        for (int w = 0; w < 8; ++w) s += sPart[w][tid];
        out[n0 + tid] = __expf(s);
    }
}

// ---------------------------------------------------------------------------
extern "C" void kernel_launch(void* const* d_in, const int* in_sizes, int n_in,
                              void* d_out, int out_size) {
    (void)in_sizes; (void)n_in; (void)out_size;
    const float* r   = (const float*)d_in[0];
    const float* rp  = (const float*)d_in[1];
    const float* cx  = (const float*)d_in[2];
    const float* cy  = (const float*)d_in[3];
    const float* Wa1 = (const float*)d_in[4];
    const float* Wa2 = (const float*)d_in[5];
    const float* Wa3 = (const float*)d_in[6];
    const float* Wp1 = (const float*)d_in[7];
    const float* bp1 = (const float*)d_in[8];
    const float* Wp2 = (const float*)d_in[9];
    const float* bp2 = (const float*)d_in[10];
    const float* Wg1 = (const float*)d_in[11];
    const float* bg1 = (const float*)d_in[12];
    const float* Wg2 = (const float*)d_in[13];
    const float* bg2 = (const float*)d_in[14];
    const float* Wg3 = (const float*)d_in[15];
    const float* bg3 = (const float*)d_in[16];
    float* out = (float*)d_out;

    pre_ca<<<8, 512>>>(cx, Wa1);
    fused_kernel<<<N_TOT / TN, 256>>>(r, rp, cy, Wa1, Wa2, Wa3,
                                      Wp1, bp1, Wp2, bp2,
                                      Wg1, bg1, Wg2, bg2, Wg3, bg3, out);
}

// round 17
// speedup vs baseline: 1.0518x; 1.0518x over previous
#include <cuda_runtime.h>

typedef unsigned long long ULL;

__device__ __forceinline__ ULL fma2(ULL a, ULL b, ULL c) {
    ULL d;
    asm("fma.rn.f32x2 %0, %1, %2, %3;" : "=l"(d) : "l"(a), "l"(b), "l"(c));
    return d;
}
__device__ __forceinline__ ULL dup2(float x) {
    ULL d;
    asm("mov.b64 %0, {%1, %1};" : "=l"(d) : "f"(x));
    return d;
}
__device__ __forceinline__ float2 unpk(ULL v) {
    float2 r;
    asm("mov.b64 {%0, %1}, %2;" : "=f"(r.x), "=f"(r.y) : "l"(v));
    return r;
}

#define N_TOT 8192
#define TN 8          // n's per block

// Scratch (static device globals — no allocation)
__device__ __align__(16) float4 g_ca4[8 * 512];   // [k2][p] : h1 cols 4k2..4k2+3

// ---------------------------------------------------------------------------
__global__ void pre_ca(const float* __restrict__ cx, const float* __restrict__ Wa1) {
    int idx = blockIdx.x * blockDim.x + threadIdx.x;   // 4096 = 512p * 8k2
    int p = idx & 511, k2 = idx >> 9;
    float x0 = cx[p * 2 + 0], x1 = cx[p * 2 + 1];
    int j = 4 * k2;
    float4 v;
    v.x = x0 * Wa1[64 + j + 0] + x1 * Wa1[96 + j + 0];
    v.y = x0 * Wa1[64 + j + 1] + x1 * Wa1[96 + j + 1];
    v.z = x0 * Wa1[64 + j + 2] + x1 * Wa1[96 + j + 2];
    v.w = x0 * Wa1[64 + j + 3] + x1 * Wa1[96 + j + 3];
    g_ca4[k2 * 512 + p] = v;
}

// one k-row step: h1 for 4 p's against a 16-j Wa2 row slice (4 LDS.128)
__device__ __forceinline__ void step4(float qs, float c0, float c1, float c2, float c3,
                                      const float* wrow, ULL acc[4][8]) {
    ULL h0 = dup2(fmaxf(qs + c0, 0.f));
    ULL h1 = dup2(fmaxf(qs + c1, 0.f));
    ULL h2 = dup2(fmaxf(qs + c2, 0.f));
    ULL h3 = dup2(fmaxf(qs + c3, 0.f));
    const ulonglong2* wr = reinterpret_cast<const ulonglong2*>(wrow);
    ulonglong2 wA = wr[0], wB = wr[1], wC = wr[2], wD = wr[3];
    acc[0][0] = fma2(h0, wA.x, acc[0][0]); acc[0][1] = fma2(h0, wA.y, acc[0][1]);
    acc[0][2] = fma2(h0, wB.x, acc[0][2]); acc[0][3] = fma2(h0, wB.y, acc[0][3]);
    acc[0][4] = fma2(h0, wC.x, acc[0][4]); acc[0][5] = fma2(h0, wC.y, acc[0][5]);
    acc[0][6] = fma2(h0, wD.x, acc[0][6]); acc[0][7] = fma2(h0, wD.y, acc[0][7]);
    acc[1][0] = fma2(h1, wA.x, acc[1][0]); acc[1][1] = fma2(h1, wA.y, acc[1][1]);
    acc[1][2] = fma2(h1, wB.x, acc[1][2]); acc[1][3] = fma2(h1, wB.y, acc[1][3]);
    acc[1][4] = fma2(h1, wC.x, acc[1][4]); acc[1][5] = fma2(h1, wC.y, acc[1][5]);
    acc[1][6] = fma2(h1, wD.x, acc[1][6]); acc[1][7] = fma2(h1, wD.y, acc[1][7]);
    acc[2][0] = fma2(h2, wA.x, acc[2][0]); acc[2][1] = fma2(h2, wA.y, acc[2][1]);
    acc[2][2] = fma2(h2, wB.x, acc[2][2]); acc[2][3] = fma2(h2, wB.y, acc[2][3]);
    acc[2][4] = fma2(h2, wC.x, acc[2][4]); acc[2][5] = fma2(h2, wC.y, acc[2][5]);
    acc[2][6] = fma2(h2, wD.x, acc[2][6]); acc[2][7] = fma2(h2, wD.y, acc[2][7]);
    acc[3][0] = fma2(h3, wA.x, acc[3][0]); acc[3][1] = fma2(h3, wA.y, acc[3][1]);
    acc[3][2] = fma2(h3, wB.x, acc[3][2]); acc[3][3] = fma2(h3, wB.y, acc[3][3]);
    acc[3][4] = fma2(h3, wC.x, acc[3][4]); acc[3][5] = fma2(h3, wC.y, acc[3][5]);
    acc[3][6] = fma2(h3, wD.x, acc[3][6]); acc[3][7] = fma2(h3, wD.y, acc[3][7]);
}

// ---------------------------------------------------------------------------
// FUSED kernel. 256 threads, 2 blocks/SM. Thread tile: 1n x 4p x 16j.
// ONE block barrier per n; no max-shift; warp-0 projection behind mainloop.
// v-reductions over 16-lane halves only (halves are duplicates; factor
// cancels in the softmax ratio; lanes 0-15 cover all 64 p's of the warp).
__global__ __launch_bounds__(256, 2) void fused_kernel(
    const float* __restrict__ r,
    const float* __restrict__ rp,
    const float* __restrict__ coeff_y,
    const float* __restrict__ Wa1,
    const float* __restrict__ Wa2,
    const float* __restrict__ Wa3,
    const float* __restrict__ Wp1, const float* __restrict__ bp1,
    const float* __restrict__ Wp2, const float* __restrict__ bp2,
    const float* __restrict__ Wg1, const float* __restrict__ bg1,
    const float* __restrict__ Wg2, const float* __restrict__ bg2,
    const float* __restrict__ Wg3, const float* __restrict__ bg3,
    float* __restrict__ out)
{
    __shared__ __align__(16) float sWa2[1024];
    __shared__ __align__(16) float2 sQa[TN][16];
    __shared__ __align__(8)  float sWa3[32];
    __shared__ float sRedP[2][8][5];             // t-parity double buffer
    __shared__ float sHp[32];                    // warp-0 private
    __shared__ float sC[TN][16];
    __shared__ float sX[TN][25];
    __shared__ __align__(16) float sG1[256 * 8];
    __shared__ float sPart[8][8];

    const int tid  = threadIdx.x;
    const int lane = tid & 31, warp = tid >> 5;
    const int pg   = warp * 16 + (lane & 15);   // 0..127
    const int jh   = lane >> 4;                 // 0 or 1
    const int n0 = blockIdx.x * TN;

#pragma unroll
    for (int i = 0; i < 4; ++i) sWa2[tid + 256 * i] = Wa2[tid + 256 * i];
    if (tid < 32) sWa3[tid] = Wa3[tid];
    if (tid < TN * 16) {
        int t = tid >> 4, k = tid & 15;
        int n = n0 + t;
        float x0 = r[n * 4 + 0], x1 = r[n * 4 + 1];
        float q0 = x0 * Wa1[2 * k]     + x1 * Wa1[32 + 2 * k];
        float q1 = x0 * Wa1[2 * k + 1] + x1 * Wa1[32 + 2 * k + 1];
        sQa[t][k] = make_float2(q0, q1);
    }
    __syncthreads();

    const float* wbase = sWa2 + 16 * jh;            // j-slice base
    const float2* w3p = reinterpret_cast<const float2*>(sWa3) + 8 * jh;
    const float4* cyp = reinterpret_cast<const float4*>(coeff_y);

    // ================= attention phase =================
#pragma unroll 1
    for (int t = 0; t < TN; ++t) {
        const float4* qa4 = reinterpret_cast<const float4*>(sQa[t]);

        ULL acc[4][8];
#pragma unroll
        for (int i = 0; i < 4; ++i)
#pragma unroll
            for (int q = 0; q < 8; ++q) acc[i][q] = 0ull;

#pragma unroll
        for (int k2 = 0; k2 < 8; ++k2) {
            float4 ca0 = g_ca4[k2 * 512 + pg];
            float4 ca1 = g_ca4[k2 * 512 + pg + 128];
            float4 ca2 = g_ca4[k2 * 512 + pg + 256];
            float4 ca3 = g_ca4[k2 * 512 + pg + 384];
            float4 qa  = qa4[k2];                     // broadcast LDS.128
            step4(qa.x, ca0.x, ca1.x, ca2.x, ca3.x, wbase + (4 * k2 + 0) * 32, acc);
            step4(qa.y, ca0.y, ca1.y, ca2.y, ca3.y, wbase + (4 * k2 + 1) * 32, acc);
            step4(qa.z, ca0.z, ca1.z, ca2.z, ca3.z, wbase + (4 * k2 + 2) * 32, acc);
            step4(qa.w, ca0.w, ca1.w, ca2.w, ca3.w, wbase + (4 * k2 + 3) * 32, acc);
        }

        // partial logits over this thread's 16 j's, for 4 p's
        float lg[4] = {0.f, 0.f, 0.f, 0.f};
#pragma unroll
        for (int q = 0; q < 8; ++q) {
            float2 w = w3p[q];
#pragma unroll
            for (int i = 0; i < 4; ++i) {
                float2 a = unpk(acc[i][q]);
                lg[i] += fmaxf(a.x, 0.f) * w.x + fmaxf(a.y, 0.f) * w.y;
            }
        }
        // combine j-halves with partner lane (lane ^ 16)
#pragma unroll
        for (int i = 0; i < 4; ++i)
            lg[i] += __shfl_xor_sync(0xffffffffu, lg[i], 16);

        // ===== epilogue: softmax WITHOUT max-shift, ONE barrier =====
        float e0 = __expf(lg[0]);
        float e1 = __expf(lg[1]);
        float e2 = __expf(lg[2]);
        float e3 = __expf(lg[3]);
        float4 cy0 = cyp[pg];
        float4 cy1 = cyp[pg + 128];
        float4 cy2 = cyp[pg + 256];
        float4 cy3 = cyp[pg + 384];
        float v0 = e0 + e1 + e2 + e3;
        float v1 = e0 * cy0.x + e1 * cy1.x + e2 * cy2.x + e3 * cy3.x;
        float v2 = e0 * cy0.y + e1 * cy1.y + e2 * cy2.y + e3 * cy3.y;
        float v3 = e0 * cy0.z + e1 * cy1.z + e2 * cy2.z + e3 * cy3.z;
        float v4 = e0 * cy0.w + e1 * cy1.w + e2 * cy2.w + e3 * cy3.w;
        // reduce over 16-lane halves only: lanes l and l^16 hold identical
        // values, and lanes 0-15 alone cover all 64 p's of the warp.
#pragma unroll
        for (int off = 8; off; off >>= 1) {
            v0 += __shfl_xor_sync(0xffffffffu, v0, off);
            v1 += __shfl_xor_sync(0xffffffffu, v1, off);
            v2 += __shfl_xor_sync(0xffffffffu, v2, off);
            v3 += __shfl_xor_sync(0xffffffffu, v3, off);
            v4 += __shfl_xor_sync(0xffffffffu, v4, off);
        }
        const int par = t & 1;
        if (lane == 0) {
            sRedP[par][warp][0] = v0; sRedP[par][warp][1] = v1;
            sRedP[par][warp][2] = v2; sRedP[par][warp][3] = v3;
            sRedP[par][warp][4] = v4;
        }
        __syncthreads();                                        // B (only one)

        // warp 0 finishes this n alone; warps 1-7 go straight to next mainloop
        if (warp == 0) {
            float pool = 0.f;
            if (lane < 5) {
#pragma unroll
                for (int w = 0; w < 8; ++w) pool += sRedP[par][w][lane];
            }
            float p0 = __shfl_sync(0xffffffffu, pool, 0);
            float p1 = __shfl_sync(0xffffffffu, pool, 1);
            float p2 = __shfl_sync(0xffffffffu, pool, 2);
            float p3 = __shfl_sync(0xffffffffu, pool, 3);
            float p4 = __shfl_sync(0xffffffffu, pool, 4);
            float inv = 1.f / p0;
            float a0 = p1 * inv, a1 = p2 * inv, a2 = p3 * inv, a3 = p4 * inv;
            float hp = bp1[lane] + a0 * Wp1[lane] + a1 * Wp1[32 + lane]
                                 + a2 * Wp1[64 + lane] + a3 * Wp1[96 + lane];
            sHp[lane] = fmaxf(hp, 0.f);
            __syncwarp();
            if (lane < 16) {
                float cv = bp2[lane];
#pragma unroll
                for (int k = 0; k < 32; ++k) cv += sHp[k] * Wp2[k * 16 + lane];
                sC[t][lane] = cv;
            }
            __syncwarp();
        }
        // sRedP hazard: warps rewrite sRedP[par] at t+2, which is after
        // barrier B(t+1); warp 0's read of sRedP[par] completes before it
        // reaches B(t+1). Parity double-buffer makes t/t+1 disjoint.
    }
    __syncthreads();     // sC complete for all 8 n's (warp 0 done)

    // ================= gate phase (fused; rows = this block's 8 n's) =======
    if (tid < TN * 24) {
        int row = tid / 24, j = tid % 24;
        int n = n0 + row;
        float v = (j < 4) ? r[n * 4 + j]
                : (j < 8) ? rp[n * 4 + (j - 4)]
                          : sC[row][j - 8];
        sX[row][j] = v;
    }
    __syncthreads();

    // Stage A: warp w -> k in [32w, 32w+32); lane -> (row = lane&7, kq = lane>>3)
    {
        const int row = lane & 7, kq = lane >> 3;   // kq 0..3
        float x[24];
#pragma unroll
        for (int j = 0; j < 24; ++j) x[j] = sX[row][j];
        const int kbase = warp * 32 + kq;
#pragma unroll 4
        for (int kk = 0; kk < 8; ++kk) {
            int k = kbase + 4 * kk;
            float a = bg1[k];
#pragma unroll
            for (int j = 0; j < 24; ++j) a += x[j] * Wg1[j * 256 + k];
            sG1[k * 8 + row] = fmaxf(a, 0.f);
        }
    }
    __syncthreads();

    // Stage B: lane owns one j column; 8 rows packed in 4 ULL accs
    const int jcol = warp * 32 + lane;

    ULL acc[4];
    {
        ULL b2 = dup2(bg2[jcol]);
#pragma unroll
        for (int i = 0; i < 4; ++i) acc[i] = b2;
    }

    const float* wcol = Wg2 + jcol;
    const ulonglong2* gRows = reinterpret_cast<const ulonglong2*>(sG1);

#pragma unroll 8
    for (int k = 0; k < 256; ++k) {
        ULL w2 = dup2(wcol[k * 256]);        // coalesced LDG.32
        ulonglong2 g01 = gRows[k * 2 + 0];   // rows 0-3 (broadcast LDS.128)
        ulonglong2 g23 = gRows[k * 2 + 1];   // rows 4-7
        acc[0] = fma2(g01.x, w2, acc[0]);
        acc[1] = fma2(g01.y, w2, acc[1]);
        acc[2] = fma2(g23.x, w2, acc[2]);
        acc[3] = fma2(g23.y, w2, acc[3]);
    }

    // epilogue: relu, * Wg3, reduce across lanes (j), then across warps
    float w3 = Wg3[jcol];
    float rv[8];
#pragma unroll
    for (int i = 0; i < 4; ++i) {
        float2 a = unpk(acc[i]);
        rv[2 * i]     = fmaxf(a.x, 0.f) * w3;
        rv[2 * i + 1] = fmaxf(a.y, 0.f) * w3;
    }
#pragma unroll
    for (int off = 16; off; off >>= 1) {
#pragma unroll
        for (int i = 0; i < 8; ++i)
            rv[i] += __shfl_xor_sync(0xffffffffu, rv[i], off);
    }
    if (lane == 0) {
#pragma unroll
        for (int i = 0; i < 8; ++i) sPart[warp][i] = rv[i];
    }
    __syncthreads();

    if (tid < 8) {
        float s = bg3[0];
#pragma unroll
        for (int w = 0; w < 8; ++w) s += sPart[w][tid];
        out[n0 + tid] = __expf(s);
    }
}

// ---------------------------------------------------------------------------
extern "C" void kernel_launch(void* const* d_in, const int* in_sizes, int n_in,
                              void* d_out, int out_size) {
    (void)in_sizes; (void)n_in; (void)out_size;
    const float* r   = (const float*)d_in[0];
    const float* rp  = (const float*)d_in[1];
    const float* cx  = (const float*)d_in[2];
    const float* cy  = (const float*)d_in[3];
    const float* Wa1 = (const float*)d_in[4];
    const float* Wa2 = (const float*)d_in[5];
    const float* Wa3 = (const float*)d_in[6];
    const float* Wp1 = (const float*)d_in[7];
    const float* bp1 = (const float*)d_in[8];
    const float* Wp2 = (const float*)d_in[9];
    const float* bp2 = (const float*)d_in[10];
    const float* Wg1 = (const float*)d_in[11];
    const float* bg1 = (const float*)d_in[12];
    const float* Wg2 = (const float*)d_in[13];
    const float* bg2 = (const float*)d_in[14];
    const float* Wg3 = (const float*)d_in[15];
    const float* bg3 = (const float*)d_in[16];
    float* out = (float*)d_out;

    pre_ca<<<8, 512>>>(cx, Wa1);
    fused_kernel<<<N_TOT / TN, 256>>>(r, rp, cy, Wa1, Wa2, Wa3,
                                      Wp1, bp1, Wp2, bp2,
                                      Wg1, bg1, Wg2, bg2, Wg3, bg3, out);
}